// round 3
// baseline (speedup 1.0000x reference)
#include <cuda_runtime.h>

typedef unsigned long long u64;

#define KS    9
#define KK    81
#define MM    16
#define JJ    8
#define CINN  64
#define COUTN 64
#define HH    64
#define WW    64
#define NB    32
#define TLW   32
#define TLH   8
#define XROWS (TLH + 8)           /* 16 */
#define XCOLS (TLW + 8)           /* 40 */
#define XPIX  (XROWS * XCOLS)     /* 640 */
#define NTHREADS 256
#define SMEM_BYTES (CINN * XPIX * 4 + KK * JJ * 8)  /* 163840 + 5184 = 169024 */

// ---- packed fp32x2 helpers (sm_100+/sm_103a) ----
__device__ __forceinline__ u64 ffma2(u64 a, u64 b, u64 c) {
    u64 d;
    asm("fma.rn.f32x2 %0, %1, %2, %3;" : "=l"(d) : "l"(a), "l"(b), "l"(c));
    return d;
}
__device__ __forceinline__ u64 pack2(float lo, float hi) {
    u64 d;
    asm("mov.b64 %0, {%1, %2};" : "=l"(d) : "f"(lo), "f"(hi));
    return d;
}
__device__ __forceinline__ float2 unpack2(u64 d) {
    float2 r;
    asm("mov.b64 {%0, %1}, %2;" : "=f"(r.x), "=f"(r.y) : "l"(d));
    return r;
}

extern __shared__ float smem_raw[];

__global__ void __launch_bounds__(NTHREADS, 1)
bessel_conv_kernel(const float* __restrict__ x,
                   const float* __restrict__ T_real,
                   const float* __restrict__ T_imag,
                   const float* __restrict__ w_r,
                   const float* __restrict__ w_i,
                   const float* __restrict__ bias,
                   float* __restrict__ out)
{
    float* xs = smem_raw;                               // [CIN][16][40]
    u64*   Ts = (u64*)(smem_raw + CINN * XPIX);         // [81][8] packed (Tr,Ti)

    const int tid   = threadIdx.x;
    const int tx    = tid & 31;
    const int ty    = tid >> 5;
    const int tileX = blockIdx.x;          // 0..1
    const int tileY = blockIdx.y;          // 0..7
    const int b     = blockIdx.z;          // 0..31

    const int gx = tileX * TLW + tx;
    const int gy = tileY * TLH + ty;

    // ---------- stage x tile (+4 halo, zero padded) ----------
    {
        const int baseY = tileY * TLH - 4;
        const int baseX = tileX * TLW - 4;
        const float* xb = x + (size_t)b * CINN * HH * WW;
        for (int idx = tid; idx < CINN * XPIX; idx += NTHREADS) {
            int cin = idx / XPIX;
            int rem = idx - cin * XPIX;
            int r   = rem / XCOLS;
            int c   = rem - r * XCOLS;
            int iy  = baseY + r;
            int ix  = baseX + c;
            float v = 0.0f;
            if (iy >= 0 && iy < HH && ix >= 0 && ix < WW)
                v = xb[(cin * HH + iy) * WW + ix];
            xs[idx] = v;
        }
    }
    __syncthreads();

    const float* xpix = xs + ty * XCOLS + tx;  // this thread's pixel base

#pragma unroll 1
    for (int chunk = 0; chunk < 2; ++chunk) {
        u64 acc[16];
#pragma unroll
        for (int t = 0; t < 16; ++t) acc[t] = 0ULL;

#pragma unroll 1
        for (int m = 0; m < MM; ++m) {
            // ---- stage T[m] as packed (Tr,Ti) pairs: Ts[k*8+j] ----
            __syncthreads();
            for (int idx = tid; idx < KK * JJ; idx += NTHREADS) {
                Ts[idx] = pack2(T_real[m * KK * JJ + idx],
                                T_imag[m * KK * JJ + idx]);
            }
            __syncthreads();

            u64 yr[16], yi[16];
#pragma unroll
            for (int t = 0; t < 16; ++t) { yr[t] = 0ULL; yi[t] = 0ULL; }

#pragma unroll 1
            for (int blk = 0; blk < CINN / 2; ++blk) {
                const int cin0 = blk * 2;

                // ---- Stage A: u[c][j] = sum_k (Tr,Ti)[k,j] * x(p+k) ----
                u64 u[2][8];
#pragma unroll
                for (int c = 0; c < 2; ++c)
#pragma unroll
                    for (int jj = 0; jj < 8; ++jj) u[c][jj] = 0ULL;

                const float* xp0 = xpix + cin0 * XPIX;
                const float* xp1 = xp0 + XPIX;

#pragma unroll 3
                for (int k1 = 0; k1 < 9; ++k1) {
#pragma unroll
                    for (int k2 = 0; k2 < 9; ++k2) {
                        const int k = k1 * 9 + k2;
                        const ulonglong2* tk = (const ulonglong2*)(Ts + k * 8);
                        ulonglong2 t01 = tk[0];
                        ulonglong2 t23 = tk[1];
                        ulonglong2 t45 = tk[2];
                        ulonglong2 t67 = tk[3];
                        float xv0 = xp0[k1 * XCOLS + k2];
                        float xv1 = xp1[k1 * XCOLS + k2];
                        u64 xd0 = pack2(xv0, xv0);
                        u64 xd1 = pack2(xv1, xv1);
                        u[0][0] = ffma2(t01.x, xd0, u[0][0]);
                        u[0][1] = ffma2(t01.y, xd0, u[0][1]);
                        u[0][2] = ffma2(t23.x, xd0, u[0][2]);
                        u[0][3] = ffma2(t23.y, xd0, u[0][3]);
                        u[0][4] = ffma2(t45.x, xd0, u[0][4]);
                        u[0][5] = ffma2(t45.y, xd0, u[0][5]);
                        u[0][6] = ffma2(t67.x, xd0, u[0][6]);
                        u[0][7] = ffma2(t67.y, xd0, u[0][7]);
                        u[1][0] = ffma2(t01.x, xd1, u[1][0]);
                        u[1][1] = ffma2(t01.y, xd1, u[1][1]);
                        u[1][2] = ffma2(t23.x, xd1, u[1][2]);
                        u[1][3] = ffma2(t23.y, xd1, u[1][3]);
                        u[1][4] = ffma2(t45.x, xd1, u[1][4]);
                        u[1][5] = ffma2(t45.y, xd1, u[1][5]);
                        u[1][6] = ffma2(t67.x, xd1, u[1][6]);
                        u[1][7] = ffma2(t67.y, xd1, u[1][7]);
                    }
                }

                // ---- Stage B: y[cout] += u * w (complex), 32 couts packed ----
#pragma unroll
                for (int c = 0; c < 2; ++c) {
                    const int cin = cin0 + c;
#pragma unroll
                    for (int jj = 0; jj < 8; ++jj) {
                        float2 uv = unpack2(u[c][jj]);
                        u64 ur2  = pack2(uv.x, uv.x);
                        u64 ui2  = pack2(uv.y, uv.y);
                        u64 nui2 = pack2(-uv.y, -uv.y);
                        const int wbase = (m * JJ + jj) * (CINN * COUTN)
                                          + cin * COUTN + chunk * 32;
                        const ulonglong2* wrp = (const ulonglong2*)(w_r + wbase);
                        const ulonglong2* wip = (const ulonglong2*)(w_i + wbase);
#pragma unroll
                        for (int q = 0; q < 8; ++q) {
                            ulonglong2 wr2 = __ldg(wrp + q);
                            ulonglong2 wi2 = __ldg(wip + q);
                            yr[2*q]   = ffma2(ur2,  wr2.x, yr[2*q]);
                            yr[2*q]   = ffma2(nui2, wi2.x, yr[2*q]);
                            yi[2*q]   = ffma2(ur2,  wi2.x, yi[2*q]);
                            yi[2*q]   = ffma2(ui2,  wr2.x, yi[2*q]);
                            yr[2*q+1] = ffma2(ur2,  wr2.y, yr[2*q+1]);
                            yr[2*q+1] = ffma2(nui2, wi2.y, yr[2*q+1]);
                            yi[2*q+1] = ffma2(ur2,  wi2.y, yi[2*q+1]);
                            yi[2*q+1] = ffma2(ui2,  wr2.y, yi[2*q+1]);
                        }
                    }
                }
            }

            // ---- epilogue for this m: acc += yr^2 + yi^2 (both lanes) ----
#pragma unroll
            for (int t = 0; t < 16; ++t) {
                acc[t] = ffma2(yr[t], yr[t], acc[t]);
                acc[t] = ffma2(yi[t], yi[t], acc[t]);
            }
        }

        // ---- write 32 couts of this chunk ----
        float* ob = out + ((size_t)b * COUTN + chunk * 32) * (HH * WW)
                        + gy * WW + gx;
#pragma unroll
        for (int t = 0; t < 16; ++t) {
            float2 a = unpack2(acc[t]);
            int co = 2 * t;
            ob[(size_t)co * (HH * WW)]       = a.x + __ldg(bias + chunk * 32 + co);
            ob[(size_t)(co + 1) * (HH * WW)] = a.y + __ldg(bias + chunk * 32 + co + 1);
        }
    }
}

extern "C" void kernel_launch(void* const* d_in, const int* in_sizes, int n_in,
                              void* d_out, int out_size)
{
    (void)in_sizes; (void)n_in; (void)out_size;
    const float* x  = (const float*)d_in[0];
    const float* Tr = (const float*)d_in[1];
    const float* Ti = (const float*)d_in[2];
    const float* wr = (const float*)d_in[3];
    const float* wi = (const float*)d_in[4];
    const float* b  = (const float*)d_in[5];
    float* out = (float*)d_out;

    cudaFuncSetAttribute(bessel_conv_kernel,
                         cudaFuncAttributeMaxDynamicSharedMemorySize, SMEM_BYTES);

    dim3 grid(WW / TLW, HH / TLH, NB);   // (2, 8, 32) = 512 CTAs
    bessel_conv_kernel<<<grid, NTHREADS, SMEM_BYTES>>>(x, Tr, Ti, wr, wi, b, out);
}

// round 4
// speedup vs baseline: 1.1755x; 1.1755x over previous
#include <cuda_runtime.h>

typedef unsigned long long u64;

#define KS    9
#define KK    81
#define MM    16
#define JJ    8
#define CINN  64
#define COUTN 64
#define HH    64
#define WW    64
#define NB    32
#define TLW   16
#define TLH   16
#define XROWS (TLH + 8)           /* 24 */
#define XCOLS (TLW + 8)           /* 24 */
#define XPIX  (XROWS * XCOLS)     /* 576 */
#define NTHREADS 256
#define SM_XF   (CINN * XPIX)      /* 36864 floats = 147456 B */
#define SM_ACCF (COUTN * NTHREADS) /* 16384 floats =  65536 B */
#define SMEM_BYTES (SM_XF * 4 + SM_ACCF * 4 + KK * JJ * 8) /* 218176 */

// ---- packed fp32x2 helpers (sm_103a) ----
__device__ __forceinline__ u64 ffma2(u64 a, u64 b, u64 c) {
    u64 d;
    asm("fma.rn.f32x2 %0, %1, %2, %3;" : "=l"(d) : "l"(a), "l"(b), "l"(c));
    return d;
}
__device__ __forceinline__ u64 pack2(float lo, float hi) {
    u64 d;
    asm("mov.b64 %0, {%1, %2};" : "=l"(d) : "f"(lo), "f"(hi));
    return d;
}
__device__ __forceinline__ float2 unpack2(u64 d) {
    float2 r;
    asm("mov.b64 {%0, %1}, %2;" : "=f"(r.x), "=f"(r.y) : "l"(d));
    return r;
}

extern __shared__ float smem_raw[];

__global__ void __launch_bounds__(NTHREADS, 1)
bessel_conv_kernel(const float* __restrict__ x,
                   const float* __restrict__ T_real,
                   const float* __restrict__ T_imag,
                   const float* __restrict__ w_r,
                   const float* __restrict__ w_i,
                   const float* __restrict__ bias,
                   float* __restrict__ out)
{
    float* xs   = smem_raw;                         // [CIN][24][24]
    float* accs = smem_raw + SM_XF;                 // [COUT][256]
    u64*   Ts   = (u64*)(smem_raw + SM_XF + SM_ACCF); // [81][8] packed (Tr,Ti)

    const int tid   = threadIdx.x;
    const int tx    = tid & 15;
    const int ty    = tid >> 4;
    const int tileX = blockIdx.x;          // 0..3
    const int tileY = blockIdx.y;          // 0..3
    const int b     = blockIdx.z;          // 0..31

    const int gx = tileX * TLW + tx;
    const int gy = tileY * TLH + ty;

    // ---------- stage x tile (+4 halo, zero padded) ----------
    {
        const int baseY = tileY * TLH - 4;
        const int baseX = tileX * TLW - 4;
        const float* xb = x + (size_t)b * CINN * HH * WW;
        for (int idx = tid; idx < SM_XF; idx += NTHREADS) {
            int cin = idx / XPIX;
            int rem = idx - cin * XPIX;
            int r   = rem / XCOLS;
            int c   = rem - r * XCOLS;
            int iy  = baseY + r;
            int ix  = baseX + c;
            float v = 0.0f;
            if (iy >= 0 && iy < HH && ix >= 0 && ix < WW)
                v = xb[(cin * HH + iy) * WW + ix];
            xs[idx] = v;
        }
        // zero the shared accumulator
        for (int idx = tid; idx < SM_ACCF; idx += NTHREADS)
            accs[idx] = 0.0f;
    }
    __syncthreads();

    const float* xpix = xs + ty * XCOLS + tx;  // this thread's pixel base

#pragma unroll 1
    for (int m = 0; m < MM; ++m) {
        // ---- stage T[m] as packed (Tr,Ti) pairs: Ts[k*8+j] ----
        __syncthreads();   // previous m's readers of Ts are done
        for (int idx = tid; idx < KK * JJ; idx += NTHREADS) {
            Ts[idx] = pack2(T_real[m * KK * JJ + idx],
                            T_imag[m * KK * JJ + idx]);
        }
        __syncthreads();

        u64 yr[32], yi[32];   // all 64 couts, packed 2-wide
#pragma unroll
        for (int t = 0; t < 32; ++t) { yr[t] = 0ULL; yi[t] = 0ULL; }

#pragma unroll 1
        for (int blk = 0; blk < CINN / 2; ++blk) {
            const int cin0 = blk * 2;

            // ---- Stage A: u[c][j] = sum_k (Tr,Ti)[k,j] * x(p+k) ----
            u64 u[2][8];
#pragma unroll
            for (int c = 0; c < 2; ++c)
#pragma unroll
                for (int jj = 0; jj < 8; ++jj) u[c][jj] = 0ULL;

            const float* xp0 = xpix + cin0 * XPIX;
            const float* xp1 = xp0 + XPIX;

#pragma unroll 3
            for (int k1 = 0; k1 < 9; ++k1) {
#pragma unroll
                for (int k2 = 0; k2 < 9; ++k2) {
                    const int k = k1 * 9 + k2;
                    const ulonglong2* tk = (const ulonglong2*)(Ts + k * 8);
                    ulonglong2 t01 = tk[0];
                    ulonglong2 t23 = tk[1];
                    ulonglong2 t45 = tk[2];
                    ulonglong2 t67 = tk[3];
                    float xv0 = xp0[k1 * XCOLS + k2];
                    float xv1 = xp1[k1 * XCOLS + k2];
                    u64 xd0 = pack2(xv0, xv0);
                    u64 xd1 = pack2(xv1, xv1);
                    u[0][0] = ffma2(t01.x, xd0, u[0][0]);
                    u[0][1] = ffma2(t01.y, xd0, u[0][1]);
                    u[0][2] = ffma2(t23.x, xd0, u[0][2]);
                    u[0][3] = ffma2(t23.y, xd0, u[0][3]);
                    u[0][4] = ffma2(t45.x, xd0, u[0][4]);
                    u[0][5] = ffma2(t45.y, xd0, u[0][5]);
                    u[0][6] = ffma2(t67.x, xd0, u[0][6]);
                    u[0][7] = ffma2(t67.y, xd0, u[0][7]);
                    u[1][0] = ffma2(t01.x, xd1, u[1][0]);
                    u[1][1] = ffma2(t01.y, xd1, u[1][1]);
                    u[1][2] = ffma2(t23.x, xd1, u[1][2]);
                    u[1][3] = ffma2(t23.y, xd1, u[1][3]);
                    u[1][4] = ffma2(t45.x, xd1, u[1][4]);
                    u[1][5] = ffma2(t45.y, xd1, u[1][5]);
                    u[1][6] = ffma2(t67.x, xd1, u[1][6]);
                    u[1][7] = ffma2(t67.y, xd1, u[1][7]);
                }
            }

            // ---- Stage B: y[0..63] += u * w (complex), all couts one pass ----
#pragma unroll
            for (int c = 0; c < 2; ++c) {
#pragma unroll
                for (int jj = 0; jj < 8; ++jj) {
                    float2 uv = unpack2(u[c][jj]);
                    u64 ur2  = pack2(uv.x, uv.x);
                    u64 ui2  = pack2(uv.y, uv.y);
                    u64 nui2 = pack2(-uv.y, -uv.y);
                    const int wbase = ((m * JJ + jj) * CINN + cin0 + c) * COUTN;
                    const ulonglong2* wrp = (const ulonglong2*)(w_r + wbase);
                    const ulonglong2* wip = (const ulonglong2*)(w_i + wbase);
#pragma unroll
                    for (int q = 0; q < 16; ++q) {
                        ulonglong2 a  = __ldg(wrp + q);
                        ulonglong2 bb = __ldg(wip + q);
                        yr[2*q]   = ffma2(ur2,  a.x,  yr[2*q]);
                        yr[2*q]   = ffma2(nui2, bb.x, yr[2*q]);
                        yi[2*q]   = ffma2(ur2,  bb.x, yi[2*q]);
                        yi[2*q]   = ffma2(ui2,  a.x,  yi[2*q]);
                        yr[2*q+1] = ffma2(ur2,  a.y,  yr[2*q+1]);
                        yr[2*q+1] = ffma2(nui2, bb.y, yr[2*q+1]);
                        yi[2*q+1] = ffma2(ur2,  bb.y, yi[2*q+1]);
                        yi[2*q+1] = ffma2(ui2,  a.y,  yi[2*q+1]);
                    }
                }
            }
        }

        // ---- epilogue for this m: acc += yr^2 + yi^2 (smem, [cout][tid]) ----
#pragma unroll
        for (int t = 0; t < 32; ++t) {
            float2 r  = unpack2(yr[t]);
            float2 im = unpack2(yi[t]);
            float* a0 = accs + (2 * t) * NTHREADS + tid;
            float* a1 = accs + (2 * t + 1) * NTHREADS + tid;
            *a0 += r.x * r.x + im.x * im.x;
            *a1 += r.y * r.y + im.y * im.y;
        }
    }

    // ---- write all 64 couts ----
    {
        float* ob = out + (size_t)b * COUTN * HH * WW + gy * WW + gx;
#pragma unroll 8
        for (int c = 0; c < COUTN; ++c) {
            ob[(size_t)c * (HH * WW)] =
                accs[c * NTHREADS + tid] + __ldg(bias + c);
        }
    }
}

extern "C" void kernel_launch(void* const* d_in, const int* in_sizes, int n_in,
                              void* d_out, int out_size)
{
    (void)in_sizes; (void)n_in; (void)out_size;
    const float* x  = (const float*)d_in[0];
    const float* Tr = (const float*)d_in[1];
    const float* Ti = (const float*)d_in[2];
    const float* wr = (const float*)d_in[3];
    const float* wi = (const float*)d_in[4];
    const float* b  = (const float*)d_in[5];
    float* out = (float*)d_out;

    cudaFuncSetAttribute(bessel_conv_kernel,
                         cudaFuncAttributeMaxDynamicSharedMemorySize, SMEM_BYTES);

    dim3 grid(WW / TLW, HH / TLH, NB);   // (4, 4, 32) = 512 CTAs
    bessel_conv_kernel<<<grid, NTHREADS, SMEM_BYTES>>>(x, Tr, Ti, wr, wi, b, out);
}

// round 5
// speedup vs baseline: 1.2068x; 1.0266x over previous
#include <cuda_runtime.h>

typedef unsigned long long u64;

#define KS    9
#define KK    81
#define MM    16
#define JJ    8
#define CINN  64
#define COUTN 64
#define HH    64
#define WW    64
#define NB    32
#define TLW   16
#define TLH   16
#define XROWS (TLH + 8)           /* 24 */
#define XCOLS (TLW + 8)           /* 24 */
#define XPIX  (XROWS * XCOLS)     /* 576 */
#define NCP   (CINN / 2)          /* 32 cin pairs */
#define NTHREADS 256
#define SM_XF2  (NCP * XPIX)       /* 18432 float2 = 147456 B */
#define SM_ACCF (COUTN * NTHREADS) /* 16384 floats =  65536 B */
#define SMEM_BYTES (SM_XF2 * 8 + SM_ACCF * 4 + KK * JJ * 8) /* 218176 */

// ---- packed fp32x2 helpers (sm_103a) ----
__device__ __forceinline__ u64 ffma2(u64 a, u64 b, u64 c) {
    u64 d;
    asm("fma.rn.f32x2 %0, %1, %2, %3;" : "=l"(d) : "l"(a), "l"(b), "l"(c));
    return d;
}
__device__ __forceinline__ u64 pack2(float lo, float hi) {
    u64 d;
    asm("mov.b64 %0, {%1, %2};" : "=l"(d) : "f"(lo), "f"(hi));
    return d;
}
__device__ __forceinline__ float2 unpack2(u64 d) {
    float2 r;
    asm("mov.b64 {%0, %1}, %2;" : "=f"(r.x), "=f"(r.y) : "l"(d));
    return r;
}
// pinned 16B global load (cannot be hoisted/reordered by ptxas)
__device__ __forceinline__ void ldg2(u64& a, u64& b, const float* p) {
    asm volatile("ld.global.nc.v2.u64 {%0, %1}, [%2];"
                 : "=l"(a), "=l"(b) : "l"(p));
}
// load 4 u64 (8 floats = 8 couts) from p + off floats
__device__ __forceinline__ void ldq(u64* dst, const float* p, int off) {
    ldg2(dst[0], dst[1], p + off);
    ldg2(dst[2], dst[3], p + off + 4);
}

extern __shared__ float smem_raw[];

__global__ void __launch_bounds__(NTHREADS, 1)
bessel_conv_kernel(const float* __restrict__ x,
                   const float* __restrict__ T_real,
                   const float* __restrict__ T_imag,
                   const float* __restrict__ w_r,
                   const float* __restrict__ w_i,
                   const float* __restrict__ bias,
                   float* __restrict__ out)
{
    float2* xs2  = (float2*)smem_raw;                    // [NCP][24][24]
    float*  accs = smem_raw + SM_XF2 * 2;                // [COUT][256]
    u64*    Ts   = (u64*)(accs + SM_ACCF);               // [81][8] packed (Tr,Ti)

    const int tid   = threadIdx.x;
    const int tx    = tid & 15;
    const int ty    = tid >> 4;
    const int tileX = blockIdx.x;          // 0..3
    const int tileY = blockIdx.y;          // 0..3
    const int b     = blockIdx.z;          // 0..31

    const int gx = tileX * TLW + tx;
    const int gy = tileY * TLH + ty;

    // ---------- stage x tile (+4 halo, zero padded), cin-paired float2 ----------
    {
        const int baseY = tileY * TLH - 4;
        const int baseX = tileX * TLW - 4;
        const float* xb = x + (size_t)b * CINN * HH * WW;
        for (int idx = tid; idx < SM_XF2; idx += NTHREADS) {
            int cp  = idx / XPIX;
            int rem = idx - cp * XPIX;
            int r   = rem / XCOLS;
            int c   = rem - r * XCOLS;
            int iy  = baseY + r;
            int ix  = baseX + c;
            float2 v = make_float2(0.0f, 0.0f);
            if (iy >= 0 && iy < HH && ix >= 0 && ix < WW) {
                const float* pb = xb + ((size_t)(2 * cp) * HH + iy) * WW + ix;
                v.x = pb[0];
                v.y = pb[(size_t)HH * WW];
            }
            xs2[idx] = v;
        }
        for (int idx = tid; idx < SM_ACCF; idx += NTHREADS)
            accs[idx] = 0.0f;
    }
    __syncthreads();

    const int pixoff = ty * XCOLS + tx;   // this thread's pixel base

#pragma unroll 1
    for (int m = 0; m < MM; ++m) {
        // ---- stage T[m] as packed (Tr,Ti) pairs: Ts[k*8+j] ----
        __syncthreads();   // previous m's readers of Ts are done
        for (int idx = tid; idx < KK * JJ; idx += NTHREADS) {
            Ts[idx] = pack2(T_real[m * KK * JJ + idx],
                            T_imag[m * KK * JJ + idx]);
        }
        __syncthreads();

        const float* wm_r = w_r + (size_t)m * JJ * CINN * COUTN;
        const float* wm_i = w_i + (size_t)m * JJ * CINN * COUTN;

        u64 yr[32], yi[32];   // all 64 couts, packed 2-wide
#pragma unroll
        for (int t = 0; t < 32; ++t) { yr[t] = 0ULL; yi[t] = 0ULL; }

#pragma unroll 1
        for (int cp = 0; cp < NCP; ++cp) {
            // ---- Stage A: u[c][j] = sum_k (Tr,Ti)[k,j] * x(p+k) ----
            u64 u[2][8];
#pragma unroll
            for (int c = 0; c < 2; ++c)
#pragma unroll
                for (int jj = 0; jj < 8; ++jj) u[c][jj] = 0ULL;

            const float2* xp = xs2 + cp * XPIX + pixoff;

#pragma unroll 3
            for (int k1 = 0; k1 < 9; ++k1) {
#pragma unroll
                for (int k2 = 0; k2 < 9; ++k2) {
                    const int k = k1 * 9 + k2;
                    const ulonglong2* tk = (const ulonglong2*)(Ts + k * 8);
                    ulonglong2 t01 = tk[0];
                    ulonglong2 t23 = tk[1];
                    ulonglong2 t45 = tk[2];
                    ulonglong2 t67 = tk[3];
                    float2 xv = xp[k1 * XCOLS + k2];   // one LDS.64, both cins
                    u64 xd0 = pack2(xv.x, xv.x);
                    u64 xd1 = pack2(xv.y, xv.y);
                    u[0][0] = ffma2(t01.x, xd0, u[0][0]);
                    u[0][1] = ffma2(t01.y, xd0, u[0][1]);
                    u[0][2] = ffma2(t23.x, xd0, u[0][2]);
                    u[0][3] = ffma2(t23.y, xd0, u[0][3]);
                    u[0][4] = ffma2(t45.x, xd0, u[0][4]);
                    u[0][5] = ffma2(t45.y, xd0, u[0][5]);
                    u[0][6] = ffma2(t67.x, xd0, u[0][6]);
                    u[0][7] = ffma2(t67.y, xd0, u[0][7]);
                    u[1][0] = ffma2(t01.x, xd1, u[1][0]);
                    u[1][1] = ffma2(t01.y, xd1, u[1][1]);
                    u[1][2] = ffma2(t23.x, xd1, u[1][2]);
                    u[1][3] = ffma2(t23.y, xd1, u[1][3]);
                    u[1][4] = ffma2(t45.x, xd1, u[1][4]);
                    u[1][5] = ffma2(t45.y, xd1, u[1][5]);
                    u[1][6] = ffma2(t67.x, xd1, u[1][6]);
                    u[1][7] = ffma2(t67.y, xd1, u[1][7]);
                }
            }

            // ---- Stage B: y[0..63] += u * w (complex), pinned pipelined loads ----
#pragma unroll
            for (int c = 0; c < 2; ++c) {
#pragma unroll
                for (int jj = 0; jj < 8; ++jj) {
                    float2 uv = unpack2(u[c][jj]);
                    u64 ur2  = pack2(uv.x, uv.x);
                    u64 ui2  = pack2(uv.y, uv.y);
                    u64 nui2 = pack2(-uv.y, -uv.y);
                    const int wbase = (jj * CINN + 2 * cp + c) * COUTN;
                    const float* wrp = wm_r + wbase;
                    const float* wip = wm_i + wbase;

                    u64 wa[2][4], wb[2][4];   // ping-pong, 8 couts per group
                    ldq(wa[0], wrp, 0);
                    ldq(wb[0], wip, 0);
#pragma unroll
                    for (int g = 0; g < 8; ++g) {
                        if (g < 7) {
                            ldq(wa[(g + 1) & 1], wrp, (g + 1) * 8);
                            ldq(wb[(g + 1) & 1], wip, (g + 1) * 8);
                        }
                        const u64* A = wa[g & 1];
                        const u64* B = wb[g & 1];
#pragma unroll
                        for (int s = 0; s < 4; ++s) {
                            const int t = 4 * g + s;
                            yr[t] = ffma2(ur2,  A[s], yr[t]);
                            yr[t] = ffma2(nui2, B[s], yr[t]);
                            yi[t] = ffma2(ur2,  B[s], yi[t]);
                            yi[t] = ffma2(ui2,  A[s], yi[t]);
                        }
                    }
                }
            }
        }

        // ---- epilogue for this m: acc += yr^2 + yi^2 (smem, [cout][tid]) ----
#pragma unroll
        for (int t = 0; t < 32; ++t) {
            float2 r  = unpack2(yr[t]);
            float2 im = unpack2(yi[t]);
            float* a0 = accs + (2 * t) * NTHREADS + tid;
            float* a1 = accs + (2 * t + 1) * NTHREADS + tid;
            *a0 += r.x * r.x + im.x * im.x;
            *a1 += r.y * r.y + im.y * im.y;
        }
    }

    // ---- write all 64 couts ----
    {
        float* ob = out + (size_t)b * COUTN * HH * WW + gy * WW + gx;
#pragma unroll 8
        for (int c = 0; c < COUTN; ++c) {
            ob[(size_t)c * (HH * WW)] =
                accs[c * NTHREADS + tid] + __ldg(bias + c);
        }
    }
}

extern "C" void kernel_launch(void* const* d_in, const int* in_sizes, int n_in,
                              void* d_out, int out_size)
{
    (void)in_sizes; (void)n_in; (void)out_size;
    const float* x  = (const float*)d_in[0];
    const float* Tr = (const float*)d_in[1];
    const float* Ti = (const float*)d_in[2];
    const float* wr = (const float*)d_in[3];
    const float* wi = (const float*)d_in[4];
    const float* b  = (const float*)d_in[5];
    float* out = (float*)d_out;

    cudaFuncSetAttribute(bessel_conv_kernel,
                         cudaFuncAttributeMaxDynamicSharedMemorySize, SMEM_BYTES);

    dim3 grid(WW / TLW, HH / TLH, NB);   // (4, 4, 32) = 512 CTAs
    bessel_conv_kernel<<<grid, NTHREADS, SMEM_BYTES>>>(x, Tr, Ti, wr, wi, b, out);
}